// round 9
// baseline (speedup 1.0000x reference)
#include <cuda_runtime.h>
#include <cuda_bf16.h>
#include <cstdint>

#define B_ 4
#define T_ 2048
#define H_ 2048
#define F_ 8192
#define M_ (B_*T_)   // 8192 tokens

// ---------------- device scratch (static; no allocations) ----------------
__device__ __nv_bfloat16 g_wkq[(size_t)F_*H_];   // ternary key weight codes
__device__ __nv_bfloat16 g_wrq[(size_t)H_*H_];   // ternary receptance weight codes
__device__ __nv_bfloat16 g_wvq[(size_t)H_*F_];   // ternary value weight codes
__device__ __nv_bfloat16 g_aK[(size_t)M_*H_];    // int8 codes of key_in (as bf16)
__device__ __nv_bfloat16 g_aR[(size_t)M_*H_];    // int8 codes of rec_in
__device__ __nv_bfloat16 g_aV[(size_t)M_*F_];    // int8 codes of k
__device__ float g_kraw[(size_t)M_*F_];          // k = relu(.)^2, fp32
__device__ float g_rbuf[(size_t)M_*H_];          // sigmoid(receptance)
__device__ float g_sK[M_], g_sR[M_], g_sV[M_];   // per-row dequant scale
__device__ float g_part[3*1024];

// ---------------- reductions ----------------
__device__ __forceinline__ float warpSum(float v){
  #pragma unroll
  for(int o=16;o;o>>=1) v += __shfl_xor_sync(0xffffffffu, v, o);
  return v;
}
__device__ __forceinline__ float warpMax(float v){
  #pragma unroll
  for(int o=16;o;o>>=1) v = fmaxf(v, __shfl_xor_sync(0xffffffffu, v, o));
  return v;
}
__device__ __forceinline__ float blkSum(float v, float* sm){
  int t = threadIdx.x, nw = blockDim.x >> 5;
  v = warpSum(v);
  if((t&31)==0) sm[t>>5] = v;
  __syncthreads();
  float r = (t < nw) ? sm[t] : 0.f;
  r = warpSum(r);
  if(t==0) sm[0] = r;
  __syncthreads();
  r = sm[0];
  __syncthreads();
  return r;
}
__device__ __forceinline__ float blkMax(float v, float* sm){
  int t = threadIdx.x, nw = blockDim.x >> 5;
  v = warpMax(v);
  if((t&31)==0) sm[t>>5] = v;
  __syncthreads();
  float r = (t < nw) ? sm[t] : 0.f;
  r = warpMax(r);
  if(t==0) sm[0] = r;
  __syncthreads();
  r = sm[0];
  __syncthreads();
  return r;
}

// ---------------- weight |w| partial sums: all 3 weights in one launch ----------------
__global__ void k_absum_all(const float* __restrict__ wk, const float* __restrict__ wr,
                            const float* __restrict__ wv){
  __shared__ float sm[32];
  int region = blockIdx.x >> 10;           // 0..2
  int lb     = blockIdx.x & 1023;
  const float* w = (region==0) ? wk : (region==1) ? wr : wv;
  int n4 = (region==0) ? (F_*H_)/4 : (region==1) ? (H_*H_)/4 : (H_*F_)/4;
  float s = 0.f;
  const float4* w4 = (const float4*)w;
  for(int i = lb*blockDim.x + threadIdx.x; i < n4; i += 1024*blockDim.x){
    float4 v = w4[i];
    s += fabsf(v.x) + fabsf(v.y) + fabsf(v.z) + fabsf(v.w);
  }
  s = blkSum(s, sm);
  if(threadIdx.x == 0) g_part[region*1024 + lb] = s;
}

// ---------------- ternary weight quantization (ws reduced per-block) ----------------
__global__ void k_quantw_all(const float* __restrict__ wk, const float* __restrict__ wr,
                             const float* __restrict__ wv){
  __shared__ float sm[32];
  int b = blockIdx.x;
  int region, lb, nblk;
  if(b < 4096){ region=0; lb=b; nblk=4096; }
  else if(b < 5120){ region=1; lb=b-4096; nblk=1024; }
  else { region=2; lb=b-5120; nblk=4096; }
  const float* w = (region==0) ? wk : (region==1) ? wr : wv;
  __nv_bfloat16* wq = (region==0) ? g_wkq : (region==1) ? g_wrq : g_wvq;
  int n4 = (region==0) ? (F_*H_)/4 : (region==1) ? (H_*H_)/4 : (H_*F_)/4;
  float cnt = (float)((size_t)n4*4);

  float p = 0.f;
  #pragma unroll
  for(int j=0;j<4;j++) p += g_part[region*1024 + threadIdx.x + j*256];
  float tot = blkSum(p, sm);
  float ws = 1.f / fmaxf(tot/cnt, 1e-5f);

  for(int i = lb*blockDim.x + threadIdx.x; i < n4; i += nblk*blockDim.x){
    float4 v = ((const float4*)w)[i];
    float q0 = fminf(fmaxf(rintf(v.x*ws), -1.f), 1.f);
    float q1 = fminf(fmaxf(rintf(v.y*ws), -1.f), 1.f);
    float q2 = fminf(fmaxf(rintf(v.z*ws), -1.f), 1.f);
    float q3 = fminf(fmaxf(rintf(v.w*ws), -1.f), 1.f);
    __nv_bfloat162* o = ((__nv_bfloat162*)wq) + 2*(size_t)i;
    o[0] = __floats2bfloat162_rn(q0, q1);
    o[1] = __floats2bfloat162_rn(q2, q3);
  }
}

// helper for GEMM: wdeq = 1/ws recomputed per block (uniform, deterministic)
__device__ __forceinline__ float wdeq_of(int region, float* sm){
  float p = 0.f;
  for(int i = threadIdx.x; i < 1024; i += blockDim.x) p += g_part[region*1024 + i];
  float tot = blkSum(p, sm);
  float cnt = (region==0) ? (float)((size_t)F_*H_) : (region==1) ? (float)((size_t)H_*H_) : (float)((size_t)H_*F_);
  return fmaxf(tot/cnt, 1e-5f);
}

// ---------------- token shift + RMSNorm + int8 activation quant ----------------
__global__ void k_actprep(const float* __restrict__ hidden,
                          const float* __restrict__ tmk, const float* __restrict__ tmr,
                          const float* __restrict__ nk,  const float* __restrict__ nr){
  __shared__ float sm[32];
  int m = blockIdx.x;
  int t = m & (T_-1);
  const float* cur = hidden + (size_t)m*H_;
  float kin[8], rin[8];
  float ssk=0.f, ssr=0.f, amk=0.f, amr=0.f;
  #pragma unroll
  for(int j=0;j<8;j++){
    int h = threadIdx.x + j*256;
    float xc = cur[h];
    float xp = (t==0) ? 0.f : cur[h - H_];
    float a = tmk[h], b = tmr[h];
    float ki = xc*a + xp*(1.f-a);
    float ri = xc*b + xp*(1.f-b);
    kin[j]=ki; rin[j]=ri;
    ssk += ki*ki; ssr += ri*ri;
    amk = fmaxf(amk, fabsf(ki*nk[h]));
    amr = fmaxf(amr, fabsf(ri*nr[h]));
  }
  float tssk = blkSum(ssk, sm);
  float tssr = blkSum(ssr, sm);
  float tamk = blkMax(amk, sm);
  float tamr = blkMax(amr, sm);
  float rk = rsqrtf(tssk*(1.f/H_) + 1e-8f);
  float rr = rsqrtf(tssr*(1.f/H_) + 1e-8f);
  float rsK = fmaxf(tamk*rk, 1e-5f);
  float rsR = fmaxf(tamr*rr, 1e-5f);
  float sk = 127.f/rsK, sr = 127.f/rsR;
  #pragma unroll
  for(int j=0;j<8;j++){
    int h = threadIdx.x + j*256;
    float qk = fminf(fmaxf(rintf(kin[j]*nk[h]*rk*sk), -128.f), 127.f);
    float qr = fminf(fmaxf(rintf(rin[j]*nr[h]*rr*sr), -128.f), 127.f);
    g_aK[(size_t)m*H_ + h] = __float2bfloat16(qk);
    g_aR[(size_t)m*H_ + h] = __float2bfloat16(qr);
  }
  if(threadIdx.x == 0){ g_sK[m] = rsK*(1.f/127.f); g_sR[m] = rsR*(1.f/127.f); }
}

// ---------------- RMSNorm + int8 quant of k rows (F=8192) ----------------
__global__ void k_quantK(const float* __restrict__ nv){
  __shared__ float sm[32];
  int m = blockIdx.x;
  const float* row = g_kraw + (size_t)m*F_;
  float v[32];
  float ss=0.f, am=0.f;
  #pragma unroll
  for(int j=0;j<32;j++){
    int h = threadIdx.x + j*256;
    float x = row[h];
    v[j] = x;
    ss += x*x;
    am = fmaxf(am, fabsf(x*nv[h]));
  }
  float tss = blkSum(ss, sm);
  float tam = blkMax(am, sm);
  float rinv = rsqrtf(tss*(1.f/F_) + 1e-8f);
  float rs = fmaxf(tam*rinv, 1e-5f);
  float s = 127.f/rs;
  #pragma unroll
  for(int j=0;j<32;j++){
    int h = threadIdx.x + j*256;
    float q = fminf(fmaxf(rintf(v[j]*nv[h]*rinv*s), -128.f), 127.f);
    g_aV[(size_t)m*F_ + h] = __float2bfloat16(q);
  }
  if(threadIdx.x == 0) g_sV[m] = rs*(1.f/127.f);
}

// ---------------- bf16 tensor-core GEMM: C[M,N] = A[M,K] * Bw[N,K]^T ----------------
// CTA tile 128x128, 4 warps in 2x2, warp tile 64x64, 3 CTAs/SM (12 warps),
// BKg=32, single-barrier 3-stage pipeline, ldmatrix.x4 fragment loads
#define BM 128
#define BN 128
#define BKg 32          // 32 bf16 elems = 64 B per row
#define LDT 40          // elems: 32 + 8 pad -> 80B row stride, conflict-free ldsm
#define NSTAGE 3
#define NTHR 128
#define STAGE_E ((BM+BN)*LDT)           // elems per stage: 10240
#define STAGE_BYTES (STAGE_E*2)         // 20480 B
#define SMEM_TOTAL (NSTAGE*STAGE_BYTES) // 61440 B  -> 3 CTAs/SM

__device__ __forceinline__ void cp16(uint32_t s, const void* g){
  asm volatile("cp.async.cg.shared.global [%0], [%1], 16;" :: "r"(s), "l"(g));
}
__device__ __forceinline__ void cp_commit(){ asm volatile("cp.async.commit_group;" ::: "memory"); }
template<int N> __device__ __forceinline__ void cp_wait(){
  asm volatile("cp.async.wait_group %0;" :: "n"(N) : "memory");
}
__device__ __forceinline__ void ldsm4(uint32_t& r0, uint32_t& r1, uint32_t& r2, uint32_t& r3,
                                      uint32_t addr){
  asm volatile("ldmatrix.sync.aligned.m8n8.x4.shared.b16 {%0,%1,%2,%3}, [%4];"
               : "=r"(r0), "=r"(r1), "=r"(r2), "=r"(r3) : "r"(addr));
}
__device__ __forceinline__ void mma16816(float* c, const uint32_t* a, const uint32_t* b){
  asm volatile(
    "mma.sync.aligned.m16n8k16.row.col.f32.bf16.bf16.f32 "
    "{%0,%1,%2,%3}, {%4,%5,%6,%7}, {%8,%9}, {%0,%1,%2,%3};\n"
    : "+f"(c[0]), "+f"(c[1]), "+f"(c[2]), "+f"(c[3])
    : "r"(a[0]), "r"(a[1]), "r"(a[2]), "r"(a[3]), "r"(b[0]), "r"(b[1]));
}

// MODE 0: key   -> g_kraw = relu(x)^2
// MODE 1: rec   -> g_rbuf = sigmoid(x)
// MODE 2: value -> Cout   = x * g_rbuf
template<int MODE>
__global__ __launch_bounds__(NTHR,3) void k_gemm(float* __restrict__ Cout){
  constexpr int Ndim = (MODE==0) ? F_ : H_;
  constexpr int Kdim = (MODE==2) ? F_ : H_;
  constexpr int NKT  = Kdim / BKg;
  constexpr int REGION = (MODE==0) ? 0 : (MODE==1) ? 1 : 2;

  const __nv_bfloat16* __restrict__ A  = (MODE==0) ? g_aK  : (MODE==1) ? g_aR  : g_aV;
  const __nv_bfloat16* __restrict__ Bw = (MODE==0) ? g_wkq : (MODE==1) ? g_wrq : g_wvq;
  const float* __restrict__ rowscale   = (MODE==0) ? g_sK  : (MODE==1) ? g_sR  : g_sV;
  float* __restrict__ C                = (MODE==0) ? g_kraw : (MODE==1) ? g_rbuf : Cout;

  extern __shared__ __align__(128) __nv_bfloat16 smem[];
  __shared__ float smr[32];

  const int tid = threadIdx.x;
  const int bm = blockIdx.y*BM, bn = blockIdx.x*BN;

  const float wdeq = wdeq_of(REGION, smr);

  // per-thread load slot: 8 chunks of 16B each covering 256 rows x 4 chunks
  auto loads = [&](int buf, int kt){
    __nv_bfloat16* st = smem + buf*STAGE_E;
    const __nv_bfloat16* Ak = A  + (size_t)bm*Kdim + kt*BKg;
    const __nv_bfloat16* Bk = Bw + (size_t)bn*Kdim + kt*BKg;
    #pragma unroll
    for(int i=0;i<8;i++){
      int chunk = tid + NTHR*i;        // 0..1023 : 256 rows x 4 x 16B
      int row = chunk >> 2;
      int kc  = (chunk & 3) << 3;      // elems: 0,8,16,24
      const __nv_bfloat16* gp = (row < BM) ? (Ak + (size_t)row*Kdim + kc)
                                           : (Bk + (size_t)(row-BM)*Kdim + kc);
      cp16((uint32_t)__cvta_generic_to_shared(st + row*LDT + kc), gp);
    }
    cp_commit();
  };

  const int warp = tid >> 5, lane = tid & 31;
  const int wm = (warp & 1) * 64;    // 2 warps in M
  const int wn = (warp >> 1) * 64;   // 2 warps in N
  const int g = lane >> 2, q = lane & 3;

  const uint32_t sbu = (uint32_t)__cvta_generic_to_shared(smem);
  const int aoff = (wm + (lane & 15))*LDT + ((lane >> 4) << 3);
  const int boff = (wn + (lane & 7) + ((lane >> 4) << 3))*LDT + (((lane >> 3) & 1) << 3);

  float acc[4][8][4];
  #pragma unroll
  for(int a0=0;a0<4;a0++)
    #pragma unroll
    for(int b0=0;b0<8;b0++)
      #pragma unroll
      for(int c0=0;c0<4;c0++) acc[a0][b0][c0]=0.f;

  loads(0, 0);
  loads(1, 1);

  #pragma unroll 1
  for(int kt=0; kt<NKT; kt++){
    cp_wait<NSTAGE-2>();               // stage kt complete
    __syncthreads();                   // stage kt visible, stage kt-1 free
    if(kt + NSTAGE - 1 < NKT) loads((kt + NSTAGE - 1) % NSTAGE, kt + NSTAGE - 1);
    else cp_commit();                  // keep group count uniform

    const int buf = kt % NSTAGE;
    const uint32_t abase = sbu + buf*STAGE_BYTES;
    const uint32_t bbase = abase + BM*LDT*2;

    #pragma unroll
    for(int ks=0; ks<2; ks++){
      const int kk = ks*16;
      uint32_t afr[4][4], bfr[8][2];
      #pragma unroll
      for(int mi=0; mi<4; mi++)
        ldsm4(afr[mi][0], afr[mi][1], afr[mi][2], afr[mi][3],
              abase + (uint32_t)(aoff + mi*16*LDT + kk)*2);
      #pragma unroll
      for(int nip=0; nip<4; nip++)
        ldsm4(bfr[2*nip][0], bfr[2*nip][1], bfr[2*nip+1][0], bfr[2*nip+1][1],
              bbase + (uint32_t)(boff + nip*16*LDT + kk)*2);
      #pragma unroll
      for(int mi=0; mi<4; mi++)
        #pragma unroll
        for(int ni=0; ni<8; ni++)
          mma16816(acc[mi][ni], afr[mi], bfr[ni]);
    }
  }

  // epilogue
  #pragma unroll
  for(int mi=0; mi<4; mi++){
    int r0 = bm + wm + mi*16 + g;
    int r1 = r0 + 8;
    float sc0 = rowscale[r0]*wdeq;
    float sc1 = rowscale[r1]*wdeq;
    #pragma unroll
    for(int ni=0; ni<8; ni++){
      int col = bn + wn + ni*8 + 2*q;
      float x0 = acc[mi][ni][0]*sc0, x1 = acc[mi][ni][1]*sc0;
      float x2 = acc[mi][ni][2]*sc1, x3 = acc[mi][ni][3]*sc1;
      if(MODE == 0){
        x0 = (x0>0.f)? x0*x0 : 0.f;  x1 = (x1>0.f)? x1*x1 : 0.f;
        x2 = (x2>0.f)? x2*x2 : 0.f;  x3 = (x3>0.f)? x3*x3 : 0.f;
      } else if(MODE == 1){
        x0 = 1.f/(1.f+expf(-x0)); x1 = 1.f/(1.f+expf(-x1));
        x2 = 1.f/(1.f+expf(-x2)); x3 = 1.f/(1.f+expf(-x3));
      } else {
        float2 m0 = *(const float2*)&g_rbuf[(size_t)r0*Ndim + col];
        float2 m1 = *(const float2*)&g_rbuf[(size_t)r1*Ndim + col];
        x0 *= m0.x; x1 *= m0.y; x2 *= m1.x; x3 *= m1.y;
      }
      *(float2*)&C[(size_t)r0*Ndim + col] = make_float2(x0, x1);
      *(float2*)&C[(size_t)r1*Ndim + col] = make_float2(x2, x3);
    }
  }
}

// ---------------- launch ----------------
extern "C" void kernel_launch(void* const* d_in, const int* in_sizes, int n_in,
                              void* d_out, int out_size){
  const float* hidden = (const float*)d_in[0];
  const float* tmk    = (const float*)d_in[1];
  const float* tmr    = (const float*)d_in[2];
  const float* w_key  = (const float*)d_in[3];
  const float* w_rec  = (const float*)d_in[4];
  const float* w_val  = (const float*)d_in[5];
  const float* nk     = (const float*)d_in[6];
  const float* nr     = (const float*)d_in[7];
  const float* nv     = (const float*)d_in[8];
  float* out = (float*)d_out;

  cudaFuncSetAttribute(k_gemm<0>, cudaFuncAttributeMaxDynamicSharedMemorySize, SMEM_TOTAL);
  cudaFuncSetAttribute(k_gemm<1>, cudaFuncAttributeMaxDynamicSharedMemorySize, SMEM_TOTAL);
  cudaFuncSetAttribute(k_gemm<2>, cudaFuncAttributeMaxDynamicSharedMemorySize, SMEM_TOTAL);

  // 1) weight |w| partials (all 3 weights, one launch)
  k_absum_all<<<3072,256>>>(w_key, w_rec, w_val);

  // 2) ternary weight codes (ws reduced in-block)
  k_quantw_all<<<9216,256>>>(w_key, w_rec, w_val);

  // 3) token-shift mix + RMSNorm + int8 codes for key_in / rec_in
  k_actprep<<<M_,256>>>(hidden, tmk, tmr, nk, nr);

  // 4) key GEMM -> relu^2 -> k (fp32)
  k_gemm<0><<<dim3(F_/BN, M_/BM), NTHR, SMEM_TOTAL>>>(nullptr);

  // 5) RMSNorm + int8 codes for k
  k_quantK<<<M_,256>>>(nv);

  // 6) receptance GEMM -> sigmoid -> r
  k_gemm<1><<<dim3(H_/BN, M_/BM), NTHR, SMEM_TOTAL>>>(nullptr);

  // 7) value GEMM -> * r -> out
  k_gemm<2><<<dim3(H_/BN, M_/BM), NTHR, SMEM_TOTAL>>>(out);
}

// round 10
// speedup vs baseline: 1.5100x; 1.5100x over previous
#include <cuda_runtime.h>
#include <cuda_bf16.h>
#include <cstdint>

#define B_ 4
#define T_ 2048
#define H_ 2048
#define F_ 8192
#define M_ (B_*T_)   // 8192 tokens

// ---------------- device scratch (static; no allocations) ----------------
__device__ __nv_bfloat16 g_wkq[(size_t)F_*H_];   // ternary key weight codes
__device__ __nv_bfloat16 g_wrq[(size_t)H_*H_];   // ternary receptance weight codes
__device__ __nv_bfloat16 g_wvq[(size_t)H_*F_];   // ternary value weight codes
__device__ __nv_bfloat16 g_aK[(size_t)M_*H_];    // int8 codes of key_in (as bf16)
__device__ __nv_bfloat16 g_aR[(size_t)M_*H_];    // int8 codes of rec_in
__device__ __nv_bfloat16 g_aV[(size_t)M_*F_];    // int8 codes of k
__device__ float g_kraw[(size_t)M_*F_];          // k = relu(.)^2, fp32
__device__ float g_rbuf[(size_t)M_*H_];          // sigmoid(receptance)
__device__ float g_sK[M_], g_sR[M_], g_sV[M_];   // per-row dequant scale
__device__ float g_part[3*1024];

// ---------------- reductions ----------------
__device__ __forceinline__ float warpSum(float v){
  #pragma unroll
  for(int o=16;o;o>>=1) v += __shfl_xor_sync(0xffffffffu, v, o);
  return v;
}
__device__ __forceinline__ float warpMax(float v){
  #pragma unroll
  for(int o=16;o;o>>=1) v = fmaxf(v, __shfl_xor_sync(0xffffffffu, v, o));
  return v;
}
__device__ __forceinline__ float blkSum(float v, float* sm){
  int t = threadIdx.x, nw = blockDim.x >> 5;
  v = warpSum(v);
  if((t&31)==0) sm[t>>5] = v;
  __syncthreads();
  float r = (t < nw) ? sm[t] : 0.f;
  r = warpSum(r);
  if(t==0) sm[0] = r;
  __syncthreads();
  r = sm[0];
  __syncthreads();
  return r;
}
__device__ __forceinline__ float blkMax(float v, float* sm){
  int t = threadIdx.x, nw = blockDim.x >> 5;
  v = warpMax(v);
  if((t&31)==0) sm[t>>5] = v;
  __syncthreads();
  float r = (t < nw) ? sm[t] : 0.f;
  r = warpMax(r);
  if(t==0) sm[0] = r;
  __syncthreads();
  r = sm[0];
  __syncthreads();
  return r;
}

// ---------------- weight |w| partial sums: all 3 weights in one launch ----------------
__global__ void k_absum_all(const float* __restrict__ wk, const float* __restrict__ wr,
                            const float* __restrict__ wv){
  __shared__ float sm[32];
  int region = blockIdx.x >> 10;           // 0..2
  int lb     = blockIdx.x & 1023;
  const float* w = (region==0) ? wk : (region==1) ? wr : wv;
  int n4 = (region==0) ? (F_*H_)/4 : (region==1) ? (H_*H_)/4 : (H_*F_)/4;
  float s = 0.f;
  const float4* w4 = (const float4*)w;
  for(int i = lb*blockDim.x + threadIdx.x; i < n4; i += 1024*blockDim.x){
    float4 v = w4[i];
    s += fabsf(v.x) + fabsf(v.y) + fabsf(v.z) + fabsf(v.w);
  }
  s = blkSum(s, sm);
  if(threadIdx.x == 0) g_part[region*1024 + lb] = s;
}

// ---------------- fused: ternary weight quant + token-shift/RMSNorm act quant -------
// blocks [0, 9216): weight quant; blocks [9216, 9216+M_): actprep
__global__ void k_prep_all(const float* __restrict__ wk, const float* __restrict__ wr,
                           const float* __restrict__ wv,
                           const float* __restrict__ hidden,
                           const float* __restrict__ tmk, const float* __restrict__ tmr,
                           const float* __restrict__ nk,  const float* __restrict__ nr){
  __shared__ float sm[32];
  int b = blockIdx.x;
  if(b < 9216){
    int region, lb, nblk;
    if(b < 4096){ region=0; lb=b; nblk=4096; }
    else if(b < 5120){ region=1; lb=b-4096; nblk=1024; }
    else { region=2; lb=b-5120; nblk=4096; }
    const float* w = (region==0) ? wk : (region==1) ? wr : wv;
    __nv_bfloat16* wq = (region==0) ? g_wkq : (region==1) ? g_wrq : g_wvq;
    int n4 = (region==0) ? (F_*H_)/4 : (region==1) ? (H_*H_)/4 : (H_*F_)/4;
    float cnt = (float)((size_t)n4*4);

    float p = 0.f;
    #pragma unroll
    for(int j=0;j<4;j++) p += g_part[region*1024 + threadIdx.x + j*256];
    float tot = blkSum(p, sm);
    float ws = 1.f / fmaxf(tot/cnt, 1e-5f);

    for(int i = lb*blockDim.x + threadIdx.x; i < n4; i += nblk*blockDim.x){
      float4 v = ((const float4*)w)[i];
      float q0 = fminf(fmaxf(rintf(v.x*ws), -1.f), 1.f);
      float q1 = fminf(fmaxf(rintf(v.y*ws), -1.f), 1.f);
      float q2 = fminf(fmaxf(rintf(v.z*ws), -1.f), 1.f);
      float q3 = fminf(fmaxf(rintf(v.w*ws), -1.f), 1.f);
      __nv_bfloat162* o = ((__nv_bfloat162*)wq) + 2*(size_t)i;
      o[0] = __floats2bfloat162_rn(q0, q1);
      o[1] = __floats2bfloat162_rn(q2, q3);
    }
  } else {
    int m = b - 9216;
    int t = m & (T_-1);
    const float* cur = hidden + (size_t)m*H_;
    float kin[8], rin[8];
    float ssk=0.f, ssr=0.f, amk=0.f, amr=0.f;
    #pragma unroll
    for(int j=0;j<8;j++){
      int h = threadIdx.x + j*256;
      float xc = cur[h];
      float xp = (t==0) ? 0.f : cur[h - H_];
      float a = tmk[h], bb = tmr[h];
      float ki = xc*a + xp*(1.f-a);
      float ri = xc*bb + xp*(1.f-bb);
      kin[j]=ki; rin[j]=ri;
      ssk += ki*ki; ssr += ri*ri;
      amk = fmaxf(amk, fabsf(ki*nk[h]));
      amr = fmaxf(amr, fabsf(ri*nr[h]));
    }
    float tssk = blkSum(ssk, sm);
    float tssr = blkSum(ssr, sm);
    float tamk = blkMax(amk, sm);
    float tamr = blkMax(amr, sm);
    float rk = rsqrtf(tssk*(1.f/H_) + 1e-8f);
    float rr = rsqrtf(tssr*(1.f/H_) + 1e-8f);
    float rsK = fmaxf(tamk*rk, 1e-5f);
    float rsR = fmaxf(tamr*rr, 1e-5f);
    float sk = 127.f/rsK, sr = 127.f/rsR;
    #pragma unroll
    for(int j=0;j<8;j++){
      int h = threadIdx.x + j*256;
      float qk = fminf(fmaxf(rintf(kin[j]*nk[h]*rk*sk), -128.f), 127.f);
      float qr = fminf(fmaxf(rintf(rin[j]*nr[h]*rr*sr), -128.f), 127.f);
      g_aK[(size_t)m*H_ + h] = __float2bfloat16(qk);
      g_aR[(size_t)m*H_ + h] = __float2bfloat16(qr);
    }
    if(threadIdx.x == 0){ g_sK[m] = rsK*(1.f/127.f); g_sR[m] = rsR*(1.f/127.f); }
  }
}

// helper for GEMM: wdeq = 1/ws recomputed per block (uniform, deterministic)
__device__ __forceinline__ float wdeq_of(int region, float* sm){
  float p = 0.f;
  for(int i = threadIdx.x; i < 1024; i += blockDim.x) p += g_part[region*1024 + i];
  float tot = blkSum(p, sm);
  float cnt = (region==0) ? (float)((size_t)F_*H_) : (region==1) ? (float)((size_t)H_*H_) : (float)((size_t)H_*F_);
  return fmaxf(tot/cnt, 1e-5f);
}

// ---------------- RMSNorm + int8 quant of k rows (F=8192) ----------------
__global__ void k_quantK(const float* __restrict__ nv){
  __shared__ float sm[32];
  int m = blockIdx.x;
  const float* row = g_kraw + (size_t)m*F_;
  float v[32];
  float ss=0.f, am=0.f;
  #pragma unroll
  for(int j=0;j<32;j++){
    int h = threadIdx.x + j*256;
    float x = row[h];
    v[j] = x;
    ss += x*x;
    am = fmaxf(am, fabsf(x*nv[h]));
  }
  float tss = blkSum(ss, sm);
  float tam = blkMax(am, sm);
  float rinv = rsqrtf(tss*(1.f/F_) + 1e-8f);
  float rs = fmaxf(tam*rinv, 1e-5f);
  float s = 127.f/rs;
  #pragma unroll
  for(int j=0;j<32;j++){
    int h = threadIdx.x + j*256;
    float q = fminf(fmaxf(rintf(v[j]*nv[h]*rinv*s), -128.f), 127.f);
    g_aV[(size_t)m*F_ + h] = __float2bfloat16(q);
  }
  if(threadIdx.x == 0) g_sV[m] = rs*(1.f/127.f);
}

// ---------------- bf16 tensor-core GEMM (R8 config) ----------------
// CTA tile 128x128, 4 warps in 2x2, warp tile 64x64, 2 CTAs/SM,
// BKg=64, single-barrier 3-stage pipeline, ldmatrix.x4 fragment loads
#define BM 128
#define BN 128
#define BKg 64          // 64 bf16 elems = 128 B per row
#define LDT 72          // elems: 64 + 8 pad -> 144B row stride, conflict-free
#define NSTAGE 3
#define NTHR 128
#define STAGE_E ((BM+BN)*LDT)           // elems per stage: 18432
#define STAGE_BYTES (STAGE_E*2)         // 36864 B
#define SMEM_TOTAL (NSTAGE*STAGE_BYTES) // 110592 B

__device__ __forceinline__ void cp16(uint32_t s, const void* g){
  asm volatile("cp.async.cg.shared.global [%0], [%1], 16;" :: "r"(s), "l"(g));
}
__device__ __forceinline__ void cp_commit(){ asm volatile("cp.async.commit_group;" ::: "memory"); }
template<int N> __device__ __forceinline__ void cp_wait(){
  asm volatile("cp.async.wait_group %0;" :: "n"(N) : "memory");
}
__device__ __forceinline__ void ldsm4(uint32_t& r0, uint32_t& r1, uint32_t& r2, uint32_t& r3,
                                      uint32_t addr){
  asm volatile("ldmatrix.sync.aligned.m8n8.x4.shared.b16 {%0,%1,%2,%3}, [%4];"
               : "=r"(r0), "=r"(r1), "=r"(r2), "=r"(r3) : "r"(addr));
}
__device__ __forceinline__ void mma16816(float* c, const uint32_t* a, const uint32_t* b){
  asm volatile(
    "mma.sync.aligned.m16n8k16.row.col.f32.bf16.bf16.f32 "
    "{%0,%1,%2,%3}, {%4,%5,%6,%7}, {%8,%9}, {%0,%1,%2,%3};\n"
    : "+f"(c[0]), "+f"(c[1]), "+f"(c[2]), "+f"(c[3])
    : "r"(a[0]), "r"(a[1]), "r"(a[2]), "r"(a[3]), "r"(b[0]), "r"(b[1]));
}

// Shared mainloop: computes acc for C[bm:bm+128, bn:bn+128] = A*Bw^T
template<int KDIM>
__device__ __forceinline__ void gemm_main(const __nv_bfloat16* __restrict__ A,
                                          const __nv_bfloat16* __restrict__ Bw,
                                          int bm, int bn,
                                          __nv_bfloat16* smem,
                                          float acc[4][8][4]){
  constexpr int NKT = KDIM / BKg;
  const int tid = threadIdx.x;

  auto loads = [&](int buf, int kt){
    __nv_bfloat16* st = smem + buf*STAGE_E;
    const __nv_bfloat16* Ak = A  + (size_t)bm*KDIM + kt*BKg;
    const __nv_bfloat16* Bk = Bw + (size_t)bn*KDIM + kt*BKg;
    #pragma unroll
    for(int i=0;i<16;i++){
      int chunk = tid + NTHR*i;        // 0..2047 : 256 rows x 8 x 16B
      int row = chunk >> 3;
      int kc  = (chunk & 7) << 3;      // elems: 0,8,...,56
      const __nv_bfloat16* gp = (row < BM) ? (Ak + (size_t)row*KDIM + kc)
                                           : (Bk + (size_t)(row-BM)*KDIM + kc);
      cp16((uint32_t)__cvta_generic_to_shared(st + row*LDT + kc), gp);
    }
    cp_commit();
  };

  const int warp = tid >> 5, lane = tid & 31;
  const int wm = (warp & 1) * 64;
  const int wn = (warp >> 1) * 64;

  const uint32_t sbu = (uint32_t)__cvta_generic_to_shared(smem);
  const int aoff = (wm + (lane & 15))*LDT + ((lane >> 4) << 3);
  const int boff = (wn + (lane & 7) + ((lane >> 4) << 3))*LDT + (((lane >> 3) & 1) << 3);

  loads(0, 0);
  loads(1, 1);

  #pragma unroll 1
  for(int kt=0; kt<NKT; kt++){
    cp_wait<NSTAGE-2>();
    __syncthreads();
    if(kt + NSTAGE - 1 < NKT) loads((kt + NSTAGE - 1) % NSTAGE, kt + NSTAGE - 1);
    else cp_commit();

    const int buf = kt % NSTAGE;
    const uint32_t abase = sbu + buf*STAGE_BYTES;
    const uint32_t bbase = abase + BM*LDT*2;

    #pragma unroll
    for(int ks=0; ks<4; ks++){
      const int kk = ks*16;
      uint32_t afr[4][4], bfr[8][2];
      #pragma unroll
      for(int mi=0; mi<4; mi++)
        ldsm4(afr[mi][0], afr[mi][1], afr[mi][2], afr[mi][3],
              abase + (uint32_t)(aoff + mi*16*LDT + kk)*2);
      #pragma unroll
      for(int nip=0; nip<4; nip++)
        ldsm4(bfr[2*nip][0], bfr[2*nip][1], bfr[2*nip+1][0], bfr[2*nip+1][1],
              bbase + (uint32_t)(boff + nip*16*LDT + kk)*2);
      #pragma unroll
      for(int mi=0; mi<4; mi++)
        #pragma unroll
        for(int ni=0; ni<8; ni++)
          mma16816(acc[mi][ni], afr[mi], bfr[ni]);
    }
  }
}

// Fused key+receptance GEMM: blockIdx.x < 64 -> key (N=F), else rec (N=H)
__global__ __launch_bounds__(NTHR,2) void k_gemm_kr(){
  extern __shared__ __align__(128) __nv_bfloat16 smem[];
  __shared__ float smr[32];

  const bool iskey = (blockIdx.x < 64);
  const int bm = blockIdx.y*BM;
  const int bn = (iskey ? blockIdx.x : (blockIdx.x - 64))*BM;
  const int Ndim = iskey ? F_ : H_;

  const __nv_bfloat16* A  = iskey ? g_aK  : g_aR;
  const __nv_bfloat16* Bw = iskey ? g_wkq : g_wrq;
  const float* rowscale   = iskey ? g_sK  : g_sR;
  float* C                = iskey ? g_kraw : g_rbuf;
  const float wdeq = wdeq_of(iskey ? 0 : 1, smr);

  float acc[4][8][4];
  #pragma unroll
  for(int a0=0;a0<4;a0++)
    #pragma unroll
    for(int b0=0;b0<8;b0++)
      #pragma unroll
      for(int c0=0;c0<4;c0++) acc[a0][b0][c0]=0.f;

  gemm_main<H_>(A, Bw, bm, bn, smem, acc);

  const int warp = threadIdx.x >> 5, lane = threadIdx.x & 31;
  const int wm = (warp & 1) * 64, wn = (warp >> 1) * 64;
  const int g = lane >> 2, q = lane & 3;

  #pragma unroll
  for(int mi=0; mi<4; mi++){
    int r0 = bm + wm + mi*16 + g;
    int r1 = r0 + 8;
    float sc0 = rowscale[r0]*wdeq;
    float sc1 = rowscale[r1]*wdeq;
    #pragma unroll
    for(int ni=0; ni<8; ni++){
      int col = bn + wn + ni*8 + 2*q;
      float x0 = acc[mi][ni][0]*sc0, x1 = acc[mi][ni][1]*sc0;
      float x2 = acc[mi][ni][2]*sc1, x3 = acc[mi][ni][3]*sc1;
      if(iskey){
        x0 = (x0>0.f)? x0*x0 : 0.f;  x1 = (x1>0.f)? x1*x1 : 0.f;
        x2 = (x2>0.f)? x2*x2 : 0.f;  x3 = (x3>0.f)? x3*x3 : 0.f;
      } else {
        x0 = 1.f/(1.f+expf(-x0)); x1 = 1.f/(1.f+expf(-x1));
        x2 = 1.f/(1.f+expf(-x2)); x3 = 1.f/(1.f+expf(-x3));
      }
      *(float2*)&C[(size_t)r0*Ndim + col] = make_float2(x0, x1);
      *(float2*)&C[(size_t)r1*Ndim + col] = make_float2(x2, x3);
    }
  }
}

// Value GEMM: out = (aV * wvq^T) * rbuf
__global__ __launch_bounds__(NTHR,2) void k_gemm_v(float* __restrict__ Cout){
  extern __shared__ __align__(128) __nv_bfloat16 smem[];
  __shared__ float smr[32];

  const int bm = blockIdx.y*BM, bn = blockIdx.x*BM;
  const float wdeq = wdeq_of(2, smr);

  float acc[4][8][4];
  #pragma unroll
  for(int a0=0;a0<4;a0++)
    #pragma unroll
    for(int b0=0;b0<8;b0++)
      #pragma unroll
      for(int c0=0;c0<4;c0++) acc[a0][b0][c0]=0.f;

  gemm_main<F_>(g_aV, g_wvq, bm, bn, smem, acc);

  const int warp = threadIdx.x >> 5, lane = threadIdx.x & 31;
  const int wm = (warp & 1) * 64, wn = (warp >> 1) * 64;
  const int g = lane >> 2, q = lane & 3;

  #pragma unroll
  for(int mi=0; mi<4; mi++){
    int r0 = bm + wm + mi*16 + g;
    int r1 = r0 + 8;
    float sc0 = g_sV[r0]*wdeq;
    float sc1 = g_sV[r1]*wdeq;
    #pragma unroll
    for(int ni=0; ni<8; ni++){
      int col = bn + wn + ni*8 + 2*q;
      float x0 = acc[mi][ni][0]*sc0, x1 = acc[mi][ni][1]*sc0;
      float x2 = acc[mi][ni][2]*sc1, x3 = acc[mi][ni][3]*sc1;
      float2 m0 = *(const float2*)&g_rbuf[(size_t)r0*H_ + col];
      float2 m1 = *(const float2*)&g_rbuf[(size_t)r1*H_ + col];
      x0 *= m0.x; x1 *= m0.y; x2 *= m1.x; x3 *= m1.y;
      *(float2*)&Cout[(size_t)r0*H_ + col] = make_float2(x0, x1);
      *(float2*)&Cout[(size_t)r1*H_ + col] = make_float2(x2, x3);
    }
  }
}

// ---------------- launch ----------------
extern "C" void kernel_launch(void* const* d_in, const int* in_sizes, int n_in,
                              void* d_out, int out_size){
  const float* hidden = (const float*)d_in[0];
  const float* tmk    = (const float*)d_in[1];
  const float* tmr    = (const float*)d_in[2];
  const float* w_key  = (const float*)d_in[3];
  const float* w_rec  = (const float*)d_in[4];
  const float* w_val  = (const float*)d_in[5];
  const float* nk     = (const float*)d_in[6];
  const float* nr     = (const float*)d_in[7];
  const float* nv     = (const float*)d_in[8];
  float* out = (float*)d_out;

  cudaFuncSetAttribute(k_gemm_kr, cudaFuncAttributeMaxDynamicSharedMemorySize, SMEM_TOTAL);
  cudaFuncSetAttribute(k_gemm_v,  cudaFuncAttributeMaxDynamicSharedMemorySize, SMEM_TOTAL);

  // 1) weight |w| partials (all 3 weights, one launch)
  k_absum_all<<<3072,256>>>(w_key, w_rec, w_val);

  // 2) fused: ternary weight codes + token-shift/RMSNorm activation quant
  k_prep_all<<<9216 + M_, 256>>>(w_key, w_rec, w_val, hidden, tmk, tmr, nk, nr);

  // 3) fused key GEMM (relu^2 -> g_kraw) + receptance GEMM (sigmoid -> g_rbuf)
  k_gemm_kr<<<dim3(64 + 16, M_/BM), NTHR, SMEM_TOTAL>>>();

  // 4) RMSNorm + int8 codes for k
  k_quantK<<<M_,256>>>(nv);

  // 5) value GEMM -> * r -> out
  k_gemm_v<<<dim3(H_/BN, M_/BM), NTHR, SMEM_TOTAL>>>(out);
}

// round 12
// speedup vs baseline: 1.5359x; 1.0172x over previous
#include <cuda_runtime.h>
#include <cuda_bf16.h>
#include <cstdint>

#define B_ 4
#define T_ 2048
#define H_ 2048
#define F_ 8192
#define M_ (B_*T_)   // 8192 tokens

// ---------------- device scratch (static; no allocations) ----------------
__device__ __nv_bfloat16 g_wkq[(size_t)F_*H_];   // ternary key weight codes
__device__ __nv_bfloat16 g_wrq[(size_t)H_*H_];   // ternary receptance weight codes
__device__ __nv_bfloat16 g_wvq[(size_t)H_*F_];   // ternary value weight codes
__device__ __nv_bfloat16 g_aK[(size_t)M_*H_];    // int8 codes of key_in (as bf16)
__device__ __nv_bfloat16 g_aR[(size_t)M_*H_];    // int8 codes of rec_in
__device__ __nv_bfloat16 g_aV[(size_t)M_*F_];    // int8 codes of k
__device__ float g_kraw[(size_t)M_*F_];          // k = relu(.)^2, fp32
__device__ float g_rbuf[(size_t)M_*H_];          // sigmoid(receptance)
__device__ float g_sK[M_], g_sR[M_], g_sV[M_];   // per-row dequant scale
__device__ float g_part[3*1024];
__device__ float g_wdeq[3];                      // per-tensor dequant scale (1/ws)

// ---------------- reductions ----------------
__device__ __forceinline__ float warpSum(float v){
  #pragma unroll
  for(int o=16;o;o>>=1) v += __shfl_xor_sync(0xffffffffu, v, o);
  return v;
}
__device__ __forceinline__ float warpMax(float v){
  #pragma unroll
  for(int o=16;o;o>>=1) v = fmaxf(v, __shfl_xor_sync(0xffffffffu, v, o));
  return v;
}
__device__ __forceinline__ float blkSum(float v, float* sm){
  int t = threadIdx.x, nw = blockDim.x >> 5;
  v = warpSum(v);
  if((t&31)==0) sm[t>>5] = v;
  __syncthreads();
  float r = (t < nw) ? sm[t] : 0.f;
  r = warpSum(r);
  if(t==0) sm[0] = r;
  __syncthreads();
  r = sm[0];
  __syncthreads();
  return r;
}
__device__ __forceinline__ float blkMax(float v, float* sm){
  int t = threadIdx.x, nw = blockDim.x >> 5;
  v = warpMax(v);
  if((t&31)==0) sm[t>>5] = v;
  __syncthreads();
  float r = (t < nw) ? sm[t] : 0.f;
  r = warpMax(r);
  if(t==0) sm[0] = r;
  __syncthreads();
  r = sm[0];
  __syncthreads();
  return r;
}

// ---------------- weight |w| partial sums: all 3 weights in one launch ----------------
__global__ void k_absum_all(const float* __restrict__ wk, const float* __restrict__ wr,
                            const float* __restrict__ wv){
  __shared__ float sm[32];
  int region = blockIdx.x >> 10;           // 0..2
  int lb     = blockIdx.x & 1023;
  const float* w = (region==0) ? wk : (region==1) ? wr : wv;
  int n4 = (region==0) ? (F_*H_)/4 : (region==1) ? (H_*H_)/4 : (H_*F_)/4;
  float s = 0.f;
  const float4* w4 = (const float4*)w;
  for(int i = lb*blockDim.x + threadIdx.x; i < n4; i += 1024*blockDim.x){
    float4 v = w4[i];
    s += fabsf(v.x) + fabsf(v.y) + fabsf(v.z) + fabsf(v.w);
  }
  s = blkSum(s, sm);
  if(threadIdx.x == 0) g_part[region*1024 + lb] = s;
}

// ---------------- fused: ternary weight quant + token-shift/RMSNorm act quant -------
// blocks [0, 9216): weight quant; blocks [9216, 9216+M_): actprep
__global__ void k_prep_all(const float* __restrict__ wk, const float* __restrict__ wr,
                           const float* __restrict__ wv,
                           const float* __restrict__ hidden,
                           const float* __restrict__ tmk, const float* __restrict__ tmr,
                           const float* __restrict__ nk,  const float* __restrict__ nr){
  __shared__ float sm[32];
  int b = blockIdx.x;
  if(b < 9216){
    int region, lb, nblk;
    if(b < 4096){ region=0; lb=b; nblk=4096; }
    else if(b < 5120){ region=1; lb=b-4096; nblk=1024; }
    else { region=2; lb=b-5120; nblk=4096; }
    const float* w = (region==0) ? wk : (region==1) ? wr : wv;
    __nv_bfloat16* wq = (region==0) ? g_wkq : (region==1) ? g_wrq : g_wvq;
    int n4 = (region==0) ? (F_*H_)/4 : (region==1) ? (H_*H_)/4 : (H_*F_)/4;
    float cnt = (float)((size_t)n4*4);

    float p = 0.f;
    #pragma unroll
    for(int j=0;j<4;j++) p += g_part[region*1024 + threadIdx.x + j*256];
    float tot = blkSum(p, sm);
    float wdeq = fmaxf(tot/cnt, 1e-5f);
    float ws = 1.f / wdeq;
    if(lb == 0 && threadIdx.x == 0) g_wdeq[region] = wdeq;

    for(int i = lb*blockDim.x + threadIdx.x; i < n4; i += nblk*blockDim.x){
      float4 v = ((const float4*)w)[i];
      float q0 = fminf(fmaxf(rintf(v.x*ws), -1.f), 1.f);
      float q1 = fminf(fmaxf(rintf(v.y*ws), -1.f), 1.f);
      float q2 = fminf(fmaxf(rintf(v.z*ws), -1.f), 1.f);
      float q3 = fminf(fmaxf(rintf(v.w*ws), -1.f), 1.f);
      __nv_bfloat162* o = ((__nv_bfloat162*)wq) + 2*(size_t)i;
      o[0] = __floats2bfloat162_rn(q0, q1);
      o[1] = __floats2bfloat162_rn(q2, q3);
    }
  } else {
    int m = b - 9216;
    int t = m & (T_-1);
    const float* cur = hidden + (size_t)m*H_;
    float kin[8], rin[8];
    float ssk=0.f, ssr=0.f, amk=0.f, amr=0.f;
    #pragma unroll
    for(int j=0;j<8;j++){
      int h = threadIdx.x + j*256;
      float xc = cur[h];
      float xp = (t==0) ? 0.f : cur[h - H_];
      float a = tmk[h], bb = tmr[h];
      float ki = xc*a + xp*(1.f-a);
      float ri = xc*bb + xp*(1.f-bb);
      kin[j]=ki; rin[j]=ri;
      ssk += ki*ki; ssr += ri*ri;
      amk = fmaxf(amk, fabsf(ki*nk[h]));
      amr = fmaxf(amr, fabsf(ri*nr[h]));
    }
    float tssk = blkSum(ssk, sm);
    float tssr = blkSum(ssr, sm);
    float tamk = blkMax(amk, sm);
    float tamr = blkMax(amr, sm);
    float rk = rsqrtf(tssk*(1.f/H_) + 1e-8f);
    float rr = rsqrtf(tssr*(1.f/H_) + 1e-8f);
    float rsK = fmaxf(tamk*rk, 1e-5f);
    float rsR = fmaxf(tamr*rr, 1e-5f);
    float sk = 127.f/rsK, sr = 127.f/rsR;
    #pragma unroll
    for(int j=0;j<8;j++){
      int h = threadIdx.x + j*256;
      float qk = fminf(fmaxf(rintf(kin[j]*nk[h]*rk*sk), -128.f), 127.f);
      float qr = fminf(fmaxf(rintf(rin[j]*nr[h]*rr*sr), -128.f), 127.f);
      g_aK[(size_t)m*H_ + h] = __float2bfloat16(qk);
      g_aR[(size_t)m*H_ + h] = __float2bfloat16(qr);
    }
    if(threadIdx.x == 0){ g_sK[m] = rsK*(1.f/127.f); g_sR[m] = rsR*(1.f/127.f); }
  }
}

// ---------------- RMSNorm + int8 quant of k rows (F=8192) ----------------
__global__ void k_quantK(const float* __restrict__ nv){
  __shared__ float sm[32];
  int m = blockIdx.x;
  const float* row = g_kraw + (size_t)m*F_;
  float v[32];
  float ss=0.f, am=0.f;
  #pragma unroll
  for(int j=0;j<32;j++){
    int h = threadIdx.x + j*256;
    float x = row[h];
    v[j] = x;
    ss += x*x;
    am = fmaxf(am, fabsf(x*nv[h]));
  }
  float tss = blkSum(ss, sm);
  float tam = blkMax(am, sm);
  float rinv = rsqrtf(tss*(1.f/F_) + 1e-8f);
  float rs = fmaxf(tam*rinv, 1e-5f);
  float s = 127.f/rs;
  #pragma unroll
  for(int j=0;j<32;j++){
    int h = threadIdx.x + j*256;
    float q = fminf(fmaxf(rintf(v[j]*nv[h]*rinv*s), -128.f), 127.f);
    g_aV[(size_t)m*F_ + h] = __float2bfloat16(q);
  }
  if(threadIdx.x == 0) g_sV[m] = rs*(1.f/127.f);
}

// ---------------- bf16 tensor-core GEMM ----------------
// CTA tile 128x128, 4 warps in 2x2, warp tile 64x64, 2 CTAs/SM,
// BKg=64, single-barrier 3-stage pipeline, ks-pair A-fragment prefetch
#define BM 128
#define BN 128
#define BKg 64          // 64 bf16 elems = 128 B per row
#define LDT 72          // elems: 64 + 8 pad -> 144B row stride, conflict-free
#define NSTAGE 3
#define NTHR 128
#define STAGE_E ((BM+BN)*LDT)           // elems per stage: 18432
#define STAGE_BYTES (STAGE_E*2)         // 36864 B
#define SMEM_TOTAL (NSTAGE*STAGE_BYTES) // 110592 B

__device__ __forceinline__ void cp16(uint32_t s, const void* g){
  asm volatile("cp.async.cg.shared.global [%0], [%1], 16;" :: "r"(s), "l"(g));
}
__device__ __forceinline__ void cp_commit(){ asm volatile("cp.async.commit_group;" ::: "memory"); }
template<int N> __device__ __forceinline__ void cp_wait(){
  asm volatile("cp.async.wait_group %0;" :: "n"(N) : "memory");
}
__device__ __forceinline__ void ldsm4(uint32_t& r0, uint32_t& r1, uint32_t& r2, uint32_t& r3,
                                      uint32_t addr){
  asm volatile("ldmatrix.sync.aligned.m8n8.x4.shared.b16 {%0,%1,%2,%3}, [%4];"
               : "=r"(r0), "=r"(r1), "=r"(r2), "=r"(r3) : "r"(addr));
}
__device__ __forceinline__ void mma16816(float* c, const uint32_t* a, const uint32_t* b){
  asm volatile(
    "mma.sync.aligned.m16n8k16.row.col.f32.bf16.bf16.f32 "
    "{%0,%1,%2,%3}, {%4,%5,%6,%7}, {%8,%9}, {%0,%1,%2,%3};\n"
    : "+f"(c[0]), "+f"(c[1]), "+f"(c[2]), "+f"(c[3])
    : "r"(a[0]), "r"(a[1]), "r"(a[2]), "r"(a[3]), "r"(b[0]), "r"(b[1]));
}

// Shared mainloop: computes acc for C[bm:bm+128, bn:bn+128] = A*Bw^T
template<int KDIM>
__device__ __forceinline__ void gemm_main(const __nv_bfloat16* __restrict__ A,
                                          const __nv_bfloat16* __restrict__ Bw,
                                          int bm, int bn,
                                          __nv_bfloat16* smem,
                                          float acc[4][8][4]){
  constexpr int NKT = KDIM / BKg;
  const int tid = threadIdx.x;

  auto loads = [&](int buf, int kt){
    __nv_bfloat16* st = smem + buf*STAGE_E;
    const __nv_bfloat16* Ak = A  + (size_t)bm*KDIM + kt*BKg;
    const __nv_bfloat16* Bk = Bw + (size_t)bn*KDIM + kt*BKg;
    #pragma unroll
    for(int i=0;i<16;i++){
      int chunk = tid + NTHR*i;        // 0..2047 : 256 rows x 8 x 16B
      int row = chunk >> 3;
      int kc  = (chunk & 7) << 3;      // elems: 0,8,...,56
      const __nv_bfloat16* gp = (row < BM) ? (Ak + (size_t)row*KDIM + kc)
                                           : (Bk + (size_t)(row-BM)*KDIM + kc);
      cp16((uint32_t)__cvta_generic_to_shared(st + row*LDT + kc), gp);
    }
    cp_commit();
  };

  const int warp = tid >> 5, lane = tid & 31;
  const int wm = (warp & 1) * 64;
  const int wn = (warp >> 1) * 64;

  const uint32_t sbu = (uint32_t)__cvta_generic_to_shared(smem);
  const int aoff = (wm + (lane & 15))*LDT + ((lane >> 4) << 3);
  const int boff = (wn + (lane & 7) + ((lane >> 4) << 3))*LDT + (((lane >> 3) & 1) << 3);

  loads(0, 0);
  loads(1, 1);

  #pragma unroll 1
  for(int kt=0; kt<NKT; kt++){
    cp_wait<NSTAGE-2>();
    __syncthreads();
    if(kt + NSTAGE - 1 < NKT) loads((kt + NSTAGE - 1) % NSTAGE, kt + NSTAGE - 1);
    else cp_commit();

    const int buf = kt % NSTAGE;
    const uint32_t abase = sbu + buf*STAGE_BYTES;
    const uint32_t bbase = abase + BM*LDT*2;

    // ks pairs: batch A-fragment ldsm for 2 ks steps (8 ldsm4 burst),
    // then per-ks B ldsm + mma (B loads for ks+1 hoistable over mma of ks)
    #pragma unroll
    for(int kp=0; kp<2; kp++){
      uint32_t afr[2][4][4];
      #pragma unroll
      for(int ks2=0; ks2<2; ks2++){
        const int kk = (kp*2 + ks2)*16;
        #pragma unroll
        for(int mi=0; mi<4; mi++)
          ldsm4(afr[ks2][mi][0], afr[ks2][mi][1], afr[ks2][mi][2], afr[ks2][mi][3],
                abase + (uint32_t)(aoff + mi*16*LDT + kk)*2);
      }
      #pragma unroll
      for(int ks2=0; ks2<2; ks2++){
        const int kk = (kp*2 + ks2)*16;
        uint32_t bfr[8][2];
        #pragma unroll
        for(int nip=0; nip<4; nip++)
          ldsm4(bfr[2*nip][0], bfr[2*nip][1], bfr[2*nip+1][0], bfr[2*nip+1][1],
                bbase + (uint32_t)(boff + nip*16*LDT + kk)*2);
        #pragma unroll
        for(int mi=0; mi<4; mi++)
          #pragma unroll
          for(int ni=0; ni<8; ni++)
            mma16816(acc[mi][ni], afr[ks2][mi], bfr[ni]);
      }
    }
  }
}

// Fused key+receptance GEMM: blockIdx.x < 64 -> key (N=F), else rec (N=H)
__global__ __launch_bounds__(NTHR,2) void k_gemm_kr(){
  extern __shared__ __align__(128) __nv_bfloat16 smem[];

  const bool iskey = (blockIdx.x < 64);
  const int bm = blockIdx.y*BM;
  const int bn = (iskey ? blockIdx.x : (blockIdx.x - 64))*BM;
  const int Ndim = iskey ? F_ : H_;

  const __nv_bfloat16* A  = iskey ? g_aK  : g_aR;
  const __nv_bfloat16* Bw = iskey ? g_wkq : g_wrq;
  const float* rowscale   = iskey ? g_sK  : g_sR;
  float* C                = iskey ? g_kraw : g_rbuf;
  const float wdeq = g_wdeq[iskey ? 0 : 1];

  float acc[4][8][4];
  #pragma unroll
  for(int a0=0;a0<4;a0++)
    #pragma unroll
    for(int b0=0;b0<8;b0++)
      #pragma unroll
      for(int c0=0;c0<4;c0++) acc[a0][b0][c0]=0.f;

  gemm_main<H_>(A, Bw, bm, bn, smem, acc);

  const int warp = threadIdx.x >> 5, lane = threadIdx.x & 31;
  const int wm = (warp & 1) * 64, wn = (warp >> 1) * 64;
  const int g = lane >> 2, q = lane & 3;

  #pragma unroll
  for(int mi=0; mi<4; mi++){
    int r0 = bm + wm + mi*16 + g;
    int r1 = r0 + 8;
    float sc0 = rowscale[r0]*wdeq;
    float sc1 = rowscale[r1]*wdeq;
    #pragma unroll
    for(int ni=0; ni<8; ni++){
      int col = bn + wn + ni*8 + 2*q;
      float x0 = acc[mi][ni][0]*sc0, x1 = acc[mi][ni][1]*sc0;
      float x2 = acc[mi][ni][2]*sc1, x3 = acc[mi][ni][3]*sc1;
      if(iskey){
        x0 = (x0>0.f)? x0*x0 : 0.f;  x1 = (x1>0.f)? x1*x1 : 0.f;
        x2 = (x2>0.f)? x2*x2 : 0.f;  x3 = (x3>0.f)? x3*x3 : 0.f;
      } else {
        x0 = 1.f/(1.f+expf(-x0)); x1 = 1.f/(1.f+expf(-x1));
        x2 = 1.f/(1.f+expf(-x2)); x3 = 1.f/(1.f+expf(-x3));
      }
      *(float2*)&C[(size_t)r0*Ndim + col] = make_float2(x0, x1);
      *(float2*)&C[(size_t)r1*Ndim + col] = make_float2(x2, x3);
    }
  }
}

// Value GEMM: out = (aV * wvq^T) * rbuf
__global__ __launch_bounds__(NTHR,2) void k_gemm_v(float* __restrict__ Cout){
  extern __shared__ __align__(128) __nv_bfloat16 smem[];

  const int bm = blockIdx.y*BM, bn = blockIdx.x*BM;
  const float wdeq = g_wdeq[2];

  float acc[4][8][4];
  #pragma unroll
  for(int a0=0;a0<4;a0++)
    #pragma unroll
    for(int b0=0;b0<8;b0++)
      #pragma unroll
      for(int c0=0;c0<4;c0++) acc[a0][b0][c0]=0.f;

  gemm_main<F_>(g_aV, g_wvq, bm, bn, smem, acc);

  const int warp = threadIdx.x >> 5, lane = threadIdx.x & 31;
  const int wm = (warp & 1) * 64, wn = (warp >> 1) * 64;
  const int g = lane >> 2, q = lane & 3;

  #pragma unroll
  for(int mi=0; mi<4; mi++){
    int r0 = bm + wm + mi*16 + g;
    int r1 = r0 + 8;
    float sc0 = g_sV[r0]*wdeq;
    float sc1 = g_sV[r1]*wdeq;
    #pragma unroll
    for(int ni=0; ni<8; ni++){
      int col = bn + wn + ni*8 + 2*q;
      float x0 = acc[mi][ni][0]*sc0, x1 = acc[mi][ni][1]*sc0;
      float x2 = acc[mi][ni][2]*sc1, x3 = acc[mi][ni][3]*sc1;
      float2 m0 = *(const float2*)&g_rbuf[(size_t)r0*H_ + col];
      float2 m1 = *(const float2*)&g_rbuf[(size_t)r1*H_ + col];
      x0 *= m0.x; x1 *= m0.y; x2 *= m1.x; x3 *= m1.y;
      *(float2*)&Cout[(size_t)r0*H_ + col] = make_float2(x0, x1);
      *(float2*)&Cout[(size_t)r1*H_ + col] = make_float2(x2, x3);
    }
  }
}

// ---------------- launch ----------------
extern "C" void kernel_launch(void* const* d_in, const int* in_sizes, int n_in,
                              void* d_out, int out_size){
  const float* hidden = (const float*)d_in[0];
  const float* tmk    = (const float*)d_in[1];
  const float* tmr    = (const float*)d_in[2];
  const float* w_key  = (const float*)d_in[3];
  const float* w_rec  = (const float*)d_in[4];
  const float* w_val  = (const float*)d_in[5];
  const float* nk     = (const float*)d_in[6];
  const float* nr     = (const float*)d_in[7];
  const float* nv     = (const float*)d_in[8];
  float* out = (float*)d_out;

  cudaFuncSetAttribute(k_gemm_kr, cudaFuncAttributeMaxDynamicSharedMemorySize, SMEM_TOTAL);
  cudaFuncSetAttribute(k_gemm_v,  cudaFuncAttributeMaxDynamicSharedMemorySize, SMEM_TOTAL);

  // 1) weight |w| partials (all 3 weights, one launch)
  k_absum_all<<<3072,256>>>(w_key, w_rec, w_val);

  // 2) fused: ternary weight codes (+ g_wdeq) + token-shift/RMSNorm activation quant
  k_prep_all<<<9216 + M_, 256>>>(w_key, w_rec, w_val, hidden, tmk, tmr, nk, nr);

  // 3) fused key GEMM (relu^2 -> g_kraw) + receptance GEMM (sigmoid -> g_rbuf)
  k_gemm_kr<<<dim3(64 + 16, M_/BM), NTHR, SMEM_TOTAL>>>();

  // 4) RMSNorm + int8 codes for k
  k_quantK<<<M_,256>>>(nv);

  // 5) value GEMM -> * r -> out
  k_gemm_v<<<dim3(H_/BN, M_/BM), NTHR, SMEM_TOTAL>>>(out);
}